// round 3
// baseline (speedup 1.0000x reference)
#include <cuda_runtime.h>
#include <cuda_fp16.h>
#include <cuda_bf16.h>

#define NN 10000      // num nodes (dataset-fixed)
#define EE 640000     // num edges
#define DD 128        // feature dim
#define NSPLIT 4      // atomic contention split factor

// ---- scratch (__device__ globals; no cudaMalloc allowed) -------------------
__device__ int   g_degcnt[NSPLIT][NN];   // out-degree counts (over row), phase-split
__device__ int   g_colcnt[NSPLIT][NN];   // in-degree counts (over col), phase-split
__device__ int   g_off[NN + 1];          // CSR offsets by col
__device__ int   g_cursor[NSPLIT][NN];   // scatter cursors, phase-split
__device__ int   g_srow[EE];             // row[] sorted by col
__device__ float g_dis[NN];              // (deg+1)^{-1/2}
__device__ __align__(16) __half g_msg[NN * DD];  // fp16 (x@W)*dis[row]

// ---------------------------------------------------------------------------
// K1: zero histograms
// ---------------------------------------------------------------------------
__global__ void k_zero(int n) {
    int i = blockIdx.x * blockDim.x + threadIdx.x;
    if (i < n) {
#pragma unroll
        for (int q = 0; q < NSPLIT; q++) {
            g_degcnt[q][i] = 0;
            g_colcnt[q][i] = 0;
        }
    }
}

// ---------------------------------------------------------------------------
// K2: phase-split histograms over row (degree) and col (CSR counts)
// ---------------------------------------------------------------------------
__global__ void k_hist(const int* __restrict__ row,
                       const int* __restrict__ col, int e, int qs) {
    int i = blockIdx.x * blockDim.x + threadIdx.x;
    if (i < e) {
        int q = i / qs;                // 0..NSPLIT-1
        atomicAdd(&g_degcnt[q][row[i]], 1);
        atomicAdd(&g_colcnt[q][col[i]], 1);
    }
}

// ---------------------------------------------------------------------------
// K3: single-block scan -> CSR offsets + phase cursors; dis = rsqrt(deg+1)
// Phase sub-ranges are laid out contiguously inside each bin, so g_srow is
// still fully sorted by col.
// ---------------------------------------------------------------------------
__global__ __launch_bounds__(1024) void k_scan(int n) {
    __shared__ int sums[1024];
    const int t = threadIdx.x;
    const int chunk = (n + 1023) / 1024;
    const int beg = t * chunk;
    const int end = min(beg + chunk, n);

    int s = 0;
    for (int i = beg; i < end; i++) {
        int tot = 0;
#pragma unroll
        for (int q = 0; q < NSPLIT; q++) tot += g_colcnt[q][i];
        s += tot;
    }
    sums[t] = s;
    __syncthreads();

    for (int off = 1; off < 1024; off <<= 1) {
        int v = (t >= off) ? sums[t - off] : 0;
        __syncthreads();
        sums[t] += v;
        __syncthreads();
    }

    int run = (t == 0) ? 0 : sums[t - 1];
    for (int i = beg; i < end; i++) {
        g_off[i] = run;
        int pos = run;
#pragma unroll
        for (int q = 0; q < NSPLIT; q++) {
            g_cursor[q][i] = pos;
            pos += g_colcnt[q][i];
        }
        run = pos;
    }
    if (end == n) g_off[n] = run;

    for (int i = t; i < n; i += 1024) {
        int deg = 1;  // self loop
#pragma unroll
        for (int q = 0; q < NSPLIT; q++) deg += g_degcnt[q][i];
        g_dis[i] = rsqrtf((float)deg);
    }
}

// ---------------------------------------------------------------------------
// K4: counting-sort scatter (phase-split cursors)
// ---------------------------------------------------------------------------
__global__ void k_sort(const int* __restrict__ row,
                       const int* __restrict__ col, int e, int qs) {
    int i = blockIdx.x * blockDim.x + threadIdx.x;
    if (i < e) {
        int q = i / qs;
        int pos = atomicAdd(&g_cursor[q][col[i]], 1);
        g_srow[pos] = row[i];
    }
}

// ---------------------------------------------------------------------------
// K5: fused GEMM + row scale -> fp16:  g_msg[i,:] = half((x[i,:] @ W)*dis[i])
// 32 rows per 128-thread block.
// ---------------------------------------------------------------------------
#define RPB 32
__global__ __launch_bounds__(128) void k_gemm(const float* __restrict__ x,
                                              const float* __restrict__ W,
                                              int n) {
    __shared__ float4 xs[RPB][DD / 4];
    const int j  = threadIdx.x;              // output column
    const int r0 = blockIdx.x * RPB;

    const float4* x4 = (const float4*)x;
#pragma unroll
    for (int i = 0; i < RPB * (DD / 4) / 128; i++) {   // 8 float4 per thread
        int idx = j + i * 128;
        int r = idx >> 5, c = idx & 31;
        int gr = r0 + r;
        xs[r][c] = (gr < n) ? x4[gr * (DD / 4) + c]
                            : make_float4(0.f, 0.f, 0.f, 0.f);
    }
    __syncthreads();

    float acc[RPB];
#pragma unroll
    for (int r = 0; r < RPB; r++) acc[r] = 0.0f;

#pragma unroll 2
    for (int k = 0; k < DD; k += 4) {
        float w0 = W[(k + 0) * DD + j];
        float w1 = W[(k + 1) * DD + j];
        float w2 = W[(k + 2) * DD + j];
        float w3 = W[(k + 3) * DD + j];
#pragma unroll
        for (int r = 0; r < RPB; r++) {
            float4 xv = xs[r][k >> 2];
            acc[r] = fmaf(xv.x, w0, acc[r]);
            acc[r] = fmaf(xv.y, w1, acc[r]);
            acc[r] = fmaf(xv.z, w2, acc[r]);
            acc[r] = fmaf(xv.w, w3, acc[r]);
        }
    }

#pragma unroll
    for (int r = 0; r < RPB; r++) {
        int gr = r0 + r;
        if (gr < n) g_msg[gr * DD + j] = __float2half_rn(acc[r] * g_dis[gr]);
    }
}

// ---------------------------------------------------------------------------
// K6: gather-reduce + finalize. One warp per node; lane l owns dims [4l,4l+4).
// out[i,:] = dis[i] * (sum_{e: col=i} msg[srow[e],:] + msg[i,:]) + bias
// msg rows read as uint2 (4 fp16), accumulated in fp32.
// ---------------------------------------------------------------------------
__device__ __forceinline__ float4 h4_to_f4(uint2 v) {
    __half2 h0 = *reinterpret_cast<__half2*>(&v.x);
    __half2 h1 = *reinterpret_cast<__half2*>(&v.y);
    float2 a = __half22float2(h0);
    float2 b = __half22float2(h1);
    return make_float4(a.x, a.y, b.x, b.y);
}

__global__ __launch_bounds__(256) void k_reduce(float* __restrict__ out,
                                                const float* __restrict__ bias,
                                                int n) {
    const int node = blockIdx.x * 8 + (threadIdx.x >> 5);
    const int lane = threadIdx.x & 31;
    if (node >= n) return;

    const uint2* m2 = (const uint2*)g_msg;   // row stride = 32 uint2
    const int beg = g_off[node];
    const int end = g_off[node + 1];

    float4 acc = h4_to_f4(m2[node * 32 + lane]);   // self-loop term
    int e = beg;
    for (; e + 4 <= end; e += 4) {
        int r0 = g_srow[e + 0];
        int r1 = g_srow[e + 1];
        int r2 = g_srow[e + 2];
        int r3 = g_srow[e + 3];
        float4 v0 = h4_to_f4(m2[r0 * 32 + lane]);
        float4 v1 = h4_to_f4(m2[r1 * 32 + lane]);
        float4 v2 = h4_to_f4(m2[r2 * 32 + lane]);
        float4 v3 = h4_to_f4(m2[r3 * 32 + lane]);
        acc.x += (v0.x + v1.x) + (v2.x + v3.x);
        acc.y += (v0.y + v1.y) + (v2.y + v3.y);
        acc.z += (v0.z + v1.z) + (v2.z + v3.z);
        acc.w += (v0.w + v1.w) + (v2.w + v3.w);
    }
    for (; e < end; e++) {
        float4 v = h4_to_f4(m2[g_srow[e] * 32 + lane]);
        acc.x += v.x; acc.y += v.y; acc.z += v.z; acc.w += v.w;
    }

    const float s = g_dis[node];
    const float4 b = ((const float4*)bias)[lane];
    float4 o;
    o.x = fmaf(s, acc.x, b.x);
    o.y = fmaf(s, acc.y, b.y);
    o.z = fmaf(s, acc.z, b.z);
    o.w = fmaf(s, acc.w, b.w);
    ((float4*)out)[node * 32 + lane] = o;
}

// ---------------------------------------------------------------------------
extern "C" void kernel_launch(void* const* d_in, const int* in_sizes, int n_in,
                              void* d_out, int out_size) {
    const float* x    = (const float*)d_in[0];
    const int*   ei   = (const int*)d_in[1];
    const float* W    = (const float*)d_in[2];
    const float* bias = (const float*)d_in[3];
    float* out = (float*)d_out;

    const int n = in_sizes[0] / DD;   // 10000
    const int e = in_sizes[1] / 2;    // 640000
    const int qs = (e + NSPLIT - 1) / NSPLIT;

    const int* row = ei;              // edge_index[0]
    const int* col = ei + e;          // edge_index[1]

    k_zero<<<(n + 255) / 256, 256>>>(n);
    k_hist<<<(e + 255) / 256, 256>>>(row, col, e, qs);
    k_scan<<<1, 1024>>>(n);
    k_sort<<<(e + 255) / 256, 256>>>(row, col, e, qs);
    k_gemm<<<(n + RPB - 1) / RPB, 128>>>(x, W, n);
    k_reduce<<<(n + 7) / 8, 256>>>(out, bias, n);
}